// round 6
// baseline (speedup 1.0000x reference)
#include <cuda_runtime.h>
#include <cstdint>
#include <cmath>

// ---------------------------------------------------------------------------
// Head_55671366091048 (sm_103a):
//   Wc = rna(W)                      (q/k/v weights, 12 MB)
//   q = rna(x) Wqc^T ; k = rna(y) Wkc^T ; vT = (rna(y) Wvc^T)^T   (fused z=3)
//   a = mask(q k^T) * d^-1/2        (strict lower, 256x256 block-skipped)
//   out = a vT^T                    (per-row-block K limit, reversed bm)
//
// tcgen05 kind::tf32 SS MMA. CTA tiles 256x256 (2 m-blocks x N=256, 512 TMEM
// cols) for stages 1-2 to amortize sync overhead (1024-cyc MMA per 32-K tile)
// and halve L2 traffic. Stage 1 converts x/y in the producer (LDG->rna->STS);
// stages 2-3 are pure cp.async (inputs already tf32-valued via epilogues).
// Guarded for the harness's compute_103 PTX pass (naive fallback, never runs).
// ---------------------------------------------------------------------------

#if defined(__CUDA_ARCH__) && defined(__CUDA_ARCH_FEAT_SM103_ALL)
#define USE_TCGEN05 1
#else
#define USE_TCGEN05 0
#endif

namespace {
constexpr int kNX = 8192;
constexpr int kNY = 8192;
constexpr int kC  = 2048;
constexpr int kD  = 512;

constexpr int KT = 32;                 // K elems per smem tile (128B rows)
constexpr int MBAR_OFF = 64;
constexpr int DATA_OFF = 1024;

constexpr uint64_t DESC_BASE =
    (uint64_t(2) << 61) | (uint64_t(1) << 46) | (uint64_t(64) << 32) |
    (uint64_t(1) << 16);

__host__ __device__ constexpr uint32_t idesc_n(int n) {
  return (1u << 4) | (2u << 7) | (2u << 10) | ((uint32_t)(n / 8) << 17) |
         (8u << 24);   // M=128 per dispatch
}
}  // namespace

__device__ float g_wqc[(size_t)kD * kC];
__device__ float g_wkc[(size_t)kD * kC];
__device__ float g_wvc[(size_t)kD * kC];
__device__ float g_q[(size_t)kNX * kD];
__device__ float g_k[(size_t)kNY * kD];
__device__ float g_vT[(size_t)kD * kNY];
__device__ float g_a[(size_t)kNX * kNY];

// ---------------------------------------------------------------------------
__device__ __forceinline__ uint32_t smem_u32(const void* p) {
  uint32_t a;
  asm("{ .reg .u64 t; cvta.to.shared.u64 t, %1; cvt.u32.u64 %0, t; }"
      : "=r"(a) : "l"(p));
  return a;
}
__device__ __forceinline__ float tf32r(float f) {
  uint32_t u;
  asm("cvt.rna.tf32.f32 %0, %1;" : "=r"(u) : "f"(f));
  return __uint_as_float(u);
}
__device__ __forceinline__ float4 tf32r4(float4 v) {
  return make_float4(tf32r(v.x), tf32r(v.y), tf32r(v.z), tf32r(v.w));
}

// one launch converts Wq, Wk, Wv
__global__ void cvt3_kernel(const float* wq, float* oq, const float* wk,
                            float* ok, const float* wv, float* ov, int n) {
  const int z = blockIdx.z;
  const float* s = (z == 0) ? wq : (z == 1) ? wk : wv;
  float* d = (z == 0) ? oq : (z == 1) ? ok : ov;
  int i = (blockIdx.x * blockDim.x + threadIdx.x) * 4;
  const int stride = gridDim.x * blockDim.x * 4;
  for (; i < n; i += stride) *(float4*)(d + i) = tf32r4(*(const float4*)(s + i));
}

#if USE_TCGEN05
__device__ __forceinline__ void mbar_init(uint32_t addr, uint32_t cnt) {
  asm volatile("mbarrier.init.shared.b64 [%0], %1;" :: "r"(addr), "r"(cnt)
               : "memory");
}
__device__ __forceinline__ void mbar_inval(uint32_t addr) {
  asm volatile("mbarrier.inval.shared.b64 [%0];" :: "r"(addr) : "memory");
}
__device__ __forceinline__ void mbar_wait(uint32_t addr, uint32_t parity) {
  uint32_t done;
  asm volatile(
      "{\n\t.reg .pred p;\n\t"
      "mbarrier.try_wait.parity.acquire.cta.shared::cta.b64 p, [%1], %2;\n\t"
      "selp.b32 %0, 1, 0, p;\n\t}"
      : "=r"(done) : "r"(addr), "r"(parity) : "memory");
  if (!done) {
    asm volatile(
        "{\n\t.reg .pred P1;\n\t"
        "WL_%=:\n\t"
        "mbarrier.try_wait.parity.acquire.cta.shared::cta.b64 P1, [%0], %1, 0x989680;\n\t"
        "@P1 bra.uni WD_%=;\n\t"
        "bra.uni WL_%=;\n\t"
        "WD_%=:\n\t}"
        :: "r"(addr), "r"(parity) : "memory");
  }
}
__device__ __forceinline__ void tmem_alloc(uint32_t smem_dst, uint32_t ncols) {
  asm volatile(
      "tcgen05.alloc.cta_group::1.sync.aligned.shared::cta.b32 [%0], %1;"
      :: "r"(smem_dst), "r"(ncols) : "memory");
}
__device__ __forceinline__ void tmem_relinq() {
  asm volatile("tcgen05.relinquish_alloc_permit.cta_group::1.sync.aligned;");
}
__device__ __forceinline__ void tmem_dealloc(uint32_t tmem, uint32_t ncols) {
  asm volatile("tcgen05.dealloc.cta_group::1.sync.aligned.b32 %0, %1;"
               :: "r"(tmem), "r"(ncols));
}
__device__ __forceinline__ void mma_tf32(uint32_t d, uint64_t ad, uint64_t bd,
                                         uint32_t idesc, bool accum) {
  uint32_t en = accum ? 1u : 0u;
  asm volatile(
      "{\n\t.reg .pred p;\n\t"
      "setp.ne.u32 p, %4, 0;\n\t"
      "tcgen05.mma.cta_group::1.kind::tf32 [%0], %1, %2, %3, {%5,%5,%5,%5}, p;\n\t}"
      :: "r"(d), "l"(ad), "l"(bd), "r"(idesc), "r"(en), "r"(0u) : "memory");
}
__device__ __forceinline__ void mma_commit(uint32_t mbar) {
  asm volatile(
      "tcgen05.commit.cta_group::1.mbarrier::arrive::one.shared::cluster.b64 [%0];"
      :: "r"(mbar) : "memory");
}
__device__ __forceinline__ void ldtm_x32(uint32_t* r, uint32_t addr) {
  asm volatile(
      "tcgen05.ld.sync.aligned.32x32b.x32.b32 "
      "{%0,%1,%2,%3,%4,%5,%6,%7,%8,%9,%10,%11,%12,%13,%14,%15,"
      "%16,%17,%18,%19,%20,%21,%22,%23,%24,%25,%26,%27,%28,%29,%30,%31}, [%32];"
      : "=r"(r[0]), "=r"(r[1]), "=r"(r[2]), "=r"(r[3]), "=r"(r[4]), "=r"(r[5]),
        "=r"(r[6]), "=r"(r[7]), "=r"(r[8]), "=r"(r[9]), "=r"(r[10]),
        "=r"(r[11]), "=r"(r[12]), "=r"(r[13]), "=r"(r[14]), "=r"(r[15]),
        "=r"(r[16]), "=r"(r[17]), "=r"(r[18]), "=r"(r[19]), "=r"(r[20]),
        "=r"(r[21]), "=r"(r[22]), "=r"(r[23]), "=r"(r[24]), "=r"(r[25]),
        "=r"(r[26]), "=r"(r[27]), "=r"(r[28]), "=r"(r[29]), "=r"(r[30]),
        "=r"(r[31])
      : "r"(addr));
}
__device__ __forceinline__ void cp16(uint32_t dst, const void* src) {
  asm volatile("cp.async.cg.shared.global [%0], [%1], 16;"
               :: "r"(dst), "l"(src) : "memory");
}
#endif  // USE_TCGEN05

#define SWZ(o) ((o) ^ (((o) >> 3) & 0x70))

#if !USE_TCGEN05 && defined(__CUDA_ARCH__)
// naive fallback GEMM core (compute_103 PTX pass only; never executes on HW)
__device__ void fb_gemm(const float* A, const float* B, float* C, int M, int N,
                        int K, int row0, int col0, int rows, int cols,
                        float scale, int mode) {
  for (int e = threadIdx.x; e < rows * cols; e += blockDim.x) {
    const int r = row0 + e / cols;
    const int c = col0 + e % cols;
    float s = 0.f;
    for (int kk = 0; kk < K; ++kk)
      s += A[(size_t)r * K + kk] * B[(size_t)c * K + kk];
    if (mode == 2) s = (c >= r) ? 0.f : s * scale;
    if (mode == 1) C[(size_t)c * M + r] = s;
    else           C[(size_t)r * N + c] = s;
  }
}
#endif

// ---------------------------------------------------------------------------
// Stage 1: fused projections.  CTA tile 256x256, K=2048.
// A (x or y) converted in-producer; B (Wc) via cp.async.  z: 0=q 1=k 2=vT.
// ---------------------------------------------------------------------------
namespace {
constexpr int P_S = 3;
constexpr int P_AB = 256 * 128;          // A tile bytes (256 rows x 128B)
constexpr int P_BB = 256 * 128;          // B tile bytes
constexpr int P_STB = P_AB + P_BB;       // 64 KB
constexpr int P_SMEM = DATA_OFF + P_S * P_STB;
}

__global__ void __launch_bounds__(256, 1)
tc_proj(const float* __restrict__ x, const float* __restrict__ y,
        const float* __restrict__ wq, const float* __restrict__ wk,
        const float* __restrict__ wv, float* __restrict__ q,
        float* __restrict__ k, float* __restrict__ vT) {
  const int z = blockIdx.z;
  const float* A = (z == 0) ? x : y;
  const float* B = (z == 0) ? wq : (z == 1) ? wk : wv;
  float* C = (z == 0) ? q : (z == 1) ? k : vT;
  const int tmode = (z == 2) ? 1 : 0;

  const int bm = blockIdx.y, bn = blockIdx.x;
  const int row0 = bm * 256, col0 = bn * 256;
  const int K = kC, nT = K / KT;
  extern __shared__ char smem[];
  const int tid = threadIdx.x;

#if USE_TCGEN05
  const uint32_t sb = smem_u32(smem);
  if (tid < 32) { tmem_alloc(sb, 512); tmem_relinq(); }
  if (tid == 0)
    for (int s = 0; s < P_S; ++s) mbar_init(sb + MBAR_OFF + 8 * s, 1);
  __syncthreads();
  uint32_t tmem;
  asm volatile("ld.shared.b32 %0, [%1];" : "=r"(tmem) : "r"(sb));

  const int r0  = tid >> 3;          // 0..31
  const int c16 = tid & 7;
  const float* Ag = A + (size_t)(row0 + r0) * K + c16 * 4;
  const float* Bg = B + (size_t)(col0 + r0) * K + c16 * 4;
  const size_t rstep = (size_t)32 * K;
  const int swb = SWZ(r0 * 128 + c16 * 16);

  float4 bufA[2][8];
  // prologue: A tiles 0,1 into regs; B tile 0 via cp.async
#pragma unroll
  for (int i = 0; i < 8; ++i) {
    bufA[0][i] = *(const float4*)(Ag + i * rstep);
    bufA[1][i] = *(const float4*)(Ag + KT + i * rstep);
  }
  {
    const uint32_t db = sb + DATA_OFF + P_AB + swb;
#pragma unroll
    for (int i = 0; i < 8; ++i) cp16(db + i * 4096, Bg + i * rstep);
  }
  asm volatile("cp.async.commit_group;" ::: "memory");

  const uint32_t ide = idesc_n(256);
  for (int t = 0; t < nT; ++t) {
    const int w = t - 2;
    if (w >= 0) mbar_wait(sb + MBAR_OFF + 8 * ((t + 1) % P_S), (w / P_S) & 1);

    // STS A tile t (cvt to tf32)
    {
      char* dst = smem + DATA_OFF + (t % P_S) * P_STB + swb;
#pragma unroll
      for (int i = 0; i < 8; ++i)
        *(float4*)(dst + i * 4096) = tf32r4(bufA[t & 1][i]);
    }
    // LDG A tile t+2
    if (t + 2 < nT) {
      const float* a = Ag + (size_t)(t + 2) * KT;
#pragma unroll
      for (int i = 0; i < 8; ++i) bufA[t & 1][i] = *(const float4*)(a + i * rstep);
    }
    // cp.async B tile t+1
    if (t + 1 < nT) {
      const uint32_t db = sb + DATA_OFF + ((t + 1) % P_S) * P_STB + P_AB + swb;
      const float* b = Bg + (size_t)(t + 1) * KT;
#pragma unroll
      for (int i = 0; i < 8; ++i) cp16(db + i * 4096, b + i * rstep);
    }
    asm volatile("cp.async.commit_group;" ::: "memory");
    asm volatile("cp.async.wait_group 1;" ::: "memory");
    asm volatile("fence.proxy.async.shared::cta;" ::: "memory");
    __syncthreads();

    if (tid == 0) {
      const int s = t % P_S;
      const uint32_t base = sb + DATA_OFF + s * P_STB;
      const uint64_t bd = DESC_BASE | (((base + P_AB) >> 4) & 0x3FFF);
#pragma unroll
      for (int ms = 0; ms < 2; ++ms) {
        const uint64_t ad = DESC_BASE | (((base + ms * 16384) >> 4) & 0x3FFF);
#pragma unroll
        for (int ks = 0; ks < 4; ++ks)
          mma_tf32(tmem + ms * 256, ad + 2 * ks, bd + 2 * ks, ide,
                   (t > 0) || (ks > 0));
      }
      mma_commit(sb + MBAR_OFF + 8 * s);
    }
  }

  mbar_wait(sb + MBAR_OFF + 8 * ((nT - 1) % P_S), ((nT - 1) / P_S) & 1);
  asm volatile("tcgen05.fence::after_thread_sync;" ::: "memory");

  const int wg = tid >> 7, sp = (tid >> 5) & 3, lane = tid & 31;
  uint32_t r[32];
#pragma unroll
  for (int ms = 0; ms < 2; ++ms) {
    const int row = row0 + ms * 128 + sp * 32 + lane;
#pragma unroll
    for (int ch = 0; ch < 4; ++ch) {
      const int colb = wg * 128 + ch * 32;
      ldtm_x32(r, tmem + ms * 256 + colb);
      asm volatile("tcgen05.wait::ld.sync.aligned;" ::: "memory");
      asm volatile("tcgen05.fence::before_thread_sync;" ::: "memory");
      if (tmode == 1) {
#pragma unroll
        for (int j = 0; j < 32; ++j)
          C[(size_t)(col0 + colb + j) * kNX + row] = tf32r(__uint_as_float(r[j]));
      } else {
        float* cp = C + (size_t)row * kD + col0 + colb;
#pragma unroll
        for (int j = 0; j < 32; ++j) cp[j] = tf32r(__uint_as_float(r[j]));
      }
    }
  }

  __syncthreads();
  if (tid == 0)
    for (int s = 0; s < P_S; ++s) mbar_inval(sb + MBAR_OFF + 8 * s);
  if (tid < 32) tmem_dealloc(tmem, 512);

#elif defined(__CUDA_ARCH__)
  (void)smem;
  fb_gemm(A, B, C, kNX, kD, K, row0, col0, 256, 256, 1.0f, tmode);
#endif
}

// ---------------------------------------------------------------------------
// Stages 2 & 3: pure cp.async GEMM (inputs already tf32-valued).
// MODE 2: 256x256 tiles, skip bn>bm, mask+scale epilogue (tf32-rounded).
// MODE 3: 128x128 tiles, K limited to (bm+1)*128, reversed bm, raw store.
// ---------------------------------------------------------------------------
template <int MSUB, int BN_, int SS, int PFv, int MODE>
__global__ void __launch_bounds__(256, 1)
tc_main(const float* __restrict__ A, const float* __restrict__ B,
        float* __restrict__ C, int M, int N, int K, float scale) {
  constexpr int BMC = 128 * MSUB;
  constexpr int ABYTES = BMC * 128;
  constexpr int BBYTES = BN_ * 128;
  constexpr int STB = ABYTES + BBYTES;
  constexpr int NA = MSUB * 4;
  constexpr int NB = BN_ / 32;
  constexpr int TM = MSUB * BN_;   // TMEM cols

  int bm = blockIdx.y;
  const int bn = blockIdx.x;
  if (MODE == 3) bm = gridDim.y - 1 - bm;
  if (MODE == 2 && bn > bm) return;

  const int row0 = bm * BMC, col0 = bn * BN_;
  const int Keff = (MODE == 3) ? min(K, (bm + 1) * BMC) : K;
  const int nT = Keff / KT;
  extern __shared__ char smem[];
  const int tid = threadIdx.x;

#if USE_TCGEN05
  const uint32_t sb = smem_u32(smem);
  if (tid < 32) { tmem_alloc(sb, TM >= 128 ? TM : 128); tmem_relinq(); }
  if (tid == 0)
    for (int s = 0; s < SS; ++s) mbar_init(sb + MBAR_OFF + 8 * s, 1);
  __syncthreads();
  uint32_t tmem;
  asm volatile("ld.shared.b32 %0, [%1];" : "=r"(tmem) : "r"(sb));

  const int r0  = tid >> 3;
  const int c16 = tid & 7;
  const float* Ag = A + (size_t)(row0 + r0) * K + c16 * 4;
  const float* Bg = B + (size_t)(col0 + r0) * K + c16 * 4;
  const size_t rstep = (size_t)32 * K;
  const int swb = SWZ(r0 * 128 + c16 * 16);

  // prologue: PFv tiles
#pragma unroll
  for (int u = 0; u < PFv; ++u) {
    if (u < nT) {
      const uint32_t da = sb + DATA_OFF + (u % SS) * STB + swb;
      const float* ag = Ag + (size_t)u * KT;
      const float* bg = Bg + (size_t)u * KT;
#pragma unroll
      for (int i = 0; i < NA; ++i) cp16(da + i * 4096, ag + i * rstep);
#pragma unroll
      for (int i = 0; i < NB; ++i)
        cp16(da + ABYTES + i * 4096, bg + i * rstep);
    }
    asm volatile("cp.async.commit_group;" ::: "memory");
  }

  const uint32_t ide = idesc_n(BN_);
  for (int t = 0; t < nT; ++t) {
    const int u = t + PFv;
    const int w = u - SS;
    if (w >= 0 && u < nT)
      mbar_wait(sb + MBAR_OFF + 8 * (u % SS), (w / SS) & 1);
    if (u < nT) {
      const uint32_t da = sb + DATA_OFF + (u % SS) * STB + swb;
      const float* ag = Ag + (size_t)u * KT;
      const float* bg = Bg + (size_t)u * KT;
#pragma unroll
      for (int i = 0; i < NA; ++i) cp16(da + i * 4096, ag + i * rstep);
#pragma unroll
      for (int i = 0; i < NB; ++i)
        cp16(da + ABYTES + i * 4096, bg + i * rstep);
    }
    asm volatile("cp.async.commit_group;" ::: "memory");
    asm volatile("cp.async.wait_group %0;" :: "n"(PFv) : "memory");
    asm volatile("fence.proxy.async.shared::cta;" ::: "memory");
    __syncthreads();

    if (tid == 0) {
      const int s = t % SS;
      const uint32_t base = sb + DATA_OFF + s * STB;
      const uint64_t bd = DESC_BASE | (((base + ABYTES) >> 4) & 0x3FFF);
#pragma unroll
      for (int ms = 0; ms < MSUB; ++ms) {
        const uint64_t ad = DESC_BASE | (((base + ms * 16384) >> 4) & 0x3FFF);
#pragma unroll
        for (int ks = 0; ks < 4; ++ks)
          mma_tf32(tmem + ms * BN_, ad + 2 * ks, bd + 2 * ks, ide,
                   (t > 0) || (ks > 0));
      }
      mma_commit(sb + MBAR_OFF + 8 * s);
    }
  }

  mbar_wait(sb + MBAR_OFF + 8 * ((nT - 1) % SS), ((nT - 1) / SS) & 1);
  asm volatile("tcgen05.fence::after_thread_sync;" ::: "memory");

  const int wg = tid >> 7, sp = (tid >> 5) & 3, lane = tid & 31;
  uint32_t r[32];
#pragma unroll
  for (int ms = 0; ms < MSUB; ++ms) {
    const int row = row0 + ms * 128 + sp * 32 + lane;
#pragma unroll
    for (int ch = 0; ch < BN_ / 64; ++ch) {
      const int colb = wg * (BN_ / 2) + ch * 32;
      ldtm_x32(r, tmem + ms * BN_ + colb);
      asm volatile("tcgen05.wait::ld.sync.aligned;" ::: "memory");
      asm volatile("tcgen05.fence::before_thread_sync;" ::: "memory");
      float* cp = C + (size_t)row * N + col0 + colb;
      if (MODE == 2) {
#pragma unroll
        for (int j = 0; j < 32; ++j) {
          const int c = col0 + colb + j;
          cp[j] = (c >= row) ? 0.0f : tf32r(__uint_as_float(r[j]) * scale);
        }
      } else {
#pragma unroll
        for (int j = 0; j < 32; ++j) cp[j] = __uint_as_float(r[j]);
      }
    }
  }

  __syncthreads();
  if (tid == 0)
    for (int s = 0; s < SS; ++s) mbar_inval(sb + MBAR_OFF + 8 * s);
  if (tid < 32) tmem_dealloc(tmem, TM >= 128 ? TM : 128);

#elif defined(__CUDA_ARCH__)
  (void)smem; (void)nT;
  // fallback: only sum over Keff, matching the tc path
  for (int e = tid; e < BMC * BN_; e += blockDim.x) {
    const int rr = row0 + e / BN_;
    const int cc = col0 + e % BN_;
    float s = 0.f;
    for (int kk = 0; kk < Keff; ++kk)
      s += A[(size_t)rr * K + kk] * B[(size_t)cc * K + kk];
    if (MODE == 2) s = (cc >= rr) ? 0.f : s * scale;
    C[(size_t)rr * N + cc] = s;
  }
#endif
}

// ---------------------------------------------------------------------------

extern "C" void kernel_launch(void* const* d_in, const int* in_sizes, int n_in,
                              void* d_out, int out_size) {
  (void)in_sizes; (void)n_in; (void)out_size;
  const float* x  = (const float*)d_in[0];
  const float* y  = (const float*)d_in[1];
  const float* Wq = (const float*)d_in[2];
  const float* Wk = (const float*)d_in[3];
  const float* Wv = (const float*)d_in[4];
  float* out = (float*)d_out;

  float *wqc, *wkc, *wvc, *q, *k, *vT, *a;
  cudaGetSymbolAddress((void**)&wqc, g_wqc);
  cudaGetSymbolAddress((void**)&wkc, g_wkc);
  cudaGetSymbolAddress((void**)&wvc, g_wvc);
  cudaGetSymbolAddress((void**)&q, g_q);
  cudaGetSymbolAddress((void**)&k, g_k);
  cudaGetSymbolAddress((void**)&vT, g_vT);
  cudaGetSymbolAddress((void**)&a, g_a);

  constexpr int S2_SMEM = DATA_OFF + 3 * (2 * 16384 + 32768);  // 193 KB
  constexpr int S3_SMEM = DATA_OFF + 6 * (16384 + 16384);      // 193 KB
  cudaFuncSetAttribute(tc_proj, cudaFuncAttributeMaxDynamicSharedMemorySize,
                       P_SMEM);
  cudaFuncSetAttribute(tc_main<2, 256, 3, 1, 2>,
                       cudaFuncAttributeMaxDynamicSharedMemorySize, S2_SMEM);
  cudaFuncSetAttribute(tc_main<1, 128, 6, 4, 3>,
                       cudaFuncAttributeMaxDynamicSharedMemorySize, S3_SMEM);

  dim3 blk(256, 1, 1);
  const float scale = 1.0f / sqrtf((float)kD);

  // Stage 0: convert weights (12 MB)
  cvt3_kernel<<<dim3(64, 1, 3), blk>>>(Wq, wqc, Wk, wkc, Wv, wvc, kD * kC);

  // Stage 1: fused projections (q, k, vT), 256x256 tiles
  tc_proj<<<dim3(kD / 256, kNX / 256, 3), blk, P_SMEM>>>(x, y, wqc, wkc, wvc,
                                                         q, k, vT);

  // Stage 2: a = mask(q k^T) * scale, 256x256 tiles, lower blocks
  tc_main<2, 256, 3, 1, 2><<<dim3(kNY / 256, kNX / 256), blk, S2_SMEM>>>(
      q, k, a, kNX, kNY, kD, scale);

  // Stage 3: out = a vT^T, 128x128 tiles, K-limited, reversed bm
  tc_main<1, 128, 6, 4, 3><<<dim3(kD / 128, kNX / 128), blk, S3_SMEM>>>(
      a, vT, out, kNX, kD, kNY, 1.0f);
}